// round 1
// baseline (speedup 1.0000x reference)
#include <cuda_runtime.h>
#include <math.h>
#include <stdint.h>

#define B_ 16
#define S_ 2048
#define H_ 1024
#define M_TOTAL (B_ * S_)   // 32768

#define BM 128
#define BN 64
#define BK 32

// Device scratch (no allocs allowed)
__device__ float g_hidb[B_ * H_];      // hidden @ W1 + bias
__device__ float g_logits[B_ * S_];    // attention logits

// ---------------------------------------------------------------------------
// fp32 -> tf32 with round-to-nearest
__device__ __forceinline__ uint32_t f2tf32(float x) {
    uint32_t r;
    asm("cvt.rna.tf32.f32 %0, %1;" : "=r"(r) : "f"(x));
    return r;
}

// m16n8k8 tf32 mma
__device__ __forceinline__ void mma_tf32(float* d, const uint32_t* a, const uint32_t* b) {
    asm volatile(
        "mma.sync.aligned.m16n8k8.row.col.f32.tf32.tf32.f32 "
        "{%0,%1,%2,%3}, {%4,%5,%6,%7}, {%8,%9}, {%0,%1,%2,%3};\n"
        : "+f"(d[0]), "+f"(d[1]), "+f"(d[2]), "+f"(d[3])
        : "r"(a[0]), "r"(a[1]), "r"(a[2]), "r"(a[3]), "r"(b[0]), "r"(b[1]));
}

// Eigen/XLA rational tanh, FMA-pipe only (no MUFU). |err| ~ 1e-7 on [-8, 8].
__device__ __forceinline__ float fast_tanh(float x) {
    x = fminf(fmaxf(x, -7.99881172f), 7.99881172f);
    float x2 = x * x;
    float p = -2.76076847742355e-16f;
    p = fmaf(p, x2, 2.00018790482477e-13f);
    p = fmaf(p, x2, -8.60467152213735e-11f);
    p = fmaf(p, x2, 5.12229709037114e-08f);
    p = fmaf(p, x2, 1.48572235717979e-05f);
    p = fmaf(p, x2, 6.37261928875436e-04f);
    p = fmaf(p, x2, 4.89352455891786e-03f);
    p = p * x;
    float q = 1.19825839466702e-06f;
    q = fmaf(q, x2, 1.18534705686654e-04f);
    q = fmaf(q, x2, 2.26843463243900e-03f);
    q = fmaf(q, x2, 4.89352518554385e-03f);
    // q in [0.00489, ~0.94] > 0: bit-trick reciprocal + 3 Newton steps (no MUFU)
    float r = __uint_as_float(0x7EF127EAu - __float_as_uint(q));
    r = r * (2.0f - q * r);
    r = r * (2.0f - q * r);
    r = r * (2.0f - q * r);
    return p * r;
}

// ---------------------------------------------------------------------------
// Kernel 1: hidb[b][n] = sum_h hidden[b][h] * W_attn[h][n] + b_attn[n]
//           + zero the logits scratch.
// grid (4, 16): x = 256-col chunk, y = batch.  fp32 exact.
__global__ __launch_bounds__(256) void prep_kernel(
    const float* __restrict__ hidden,
    const float* __restrict__ W_attn,
    const float* __restrict__ b_attn)
{
    __shared__ float sh[H_];
    int b = blockIdx.y;
    int n = blockIdx.x * 256 + threadIdx.x;
    for (int i = threadIdx.x; i < H_; i += 256) sh[i] = hidden[b * H_ + i];
    __syncthreads();

    float acc = b_attn[n];
    const float* w = W_attn + n;
    #pragma unroll 16
    for (int h = 0; h < H_; ++h) acc = fmaf(sh[h], w[h * H_], acc);
    g_hidb[b * H_ + n] = acc;

    // zero logits: 16384 threads, 2 each
    int t = (blockIdx.y * 4 + blockIdx.x) * 256 + threadIdx.x;
    g_logits[t] = 0.0f;
    g_logits[t + 16384] = 0.0f;
}

// ---------------------------------------------------------------------------
// Kernel 2: fused tf32 GEMM (enc @ W2) + tanh(.+hidb) dot v -> atomicAdd logits
// grid (N/BN=16, M/BM=256), 256 threads (8 warps as 4(m) x 2(n), warp tile 32x32)
__global__ __launch_bounds__(256) void attn_gemm_kernel(
    const float* __restrict__ enc,    // (32768, 1024)
    const float* __restrict__ W2,     // (1024, 1024) == W_attn rows [H, 2H)
    const float* __restrict__ v)      // (1024,)
{
    // Padded smem: conflict-free fragment reads
    //   As row stride 36 (36%32==4): bank = (4*(lane>>2) + lane&3) -> 32 distinct
    //   Bs row stride 72 (72%32==8): bank = (8*(lane&3) + lane>>2) -> 32 distinct
    __shared__ __align__(16) uint32_t As[BM * 36];
    __shared__ __align__(16) uint32_t Bs[BK * 72];

    const int m0 = blockIdx.y * BM;
    const int n0 = blockIdx.x * BN;
    const int tid = threadIdx.x;
    const int lane = tid & 31;
    const int warp = tid >> 5;
    const int wm = warp >> 1;   // 0..3, 32-row slab
    const int wn = warp & 1;    // 0..1, 32-col slab
    const int r = lane >> 2;    // 0..7
    const int c = lane & 3;     // 0..3

    float acc[2][4][4];
    #pragma unroll
    for (int mm = 0; mm < 2; ++mm)
        #pragma unroll
        for (int nn = 0; nn < 4; ++nn)
            #pragma unroll
            for (int i = 0; i < 4; ++i) acc[mm][nn][i] = 0.0f;

    for (int kt = 0; kt < H_; kt += BK) {
        __syncthreads();
        // Load A tile: 128x32 fp32 -> tf32 (1024 float4, 4 per thread)
        #pragma unroll
        for (int p = 0; p < 4; ++p) {
            int idx = tid + p * 256;
            int row = idx >> 3;
            int q = (idx & 7) << 2;
            float4 val = *reinterpret_cast<const float4*>(&enc[(m0 + row) * H_ + kt + q]);
            uint4 u;
            u.x = f2tf32(val.x); u.y = f2tf32(val.y);
            u.z = f2tf32(val.z); u.w = f2tf32(val.w);
            *reinterpret_cast<uint4*>(&As[row * 36 + q]) = u;
        }
        // Load B tile: 32x64 fp32 -> tf32 (512 float4, 2 per thread)
        #pragma unroll
        for (int p = 0; p < 2; ++p) {
            int idx = tid + p * 256;
            int row = idx >> 4;
            int q = (idx & 15) << 2;
            float4 val = *reinterpret_cast<const float4*>(&W2[(kt + row) * H_ + n0 + q]);
            uint4 u;
            u.x = f2tf32(val.x); u.y = f2tf32(val.y);
            u.z = f2tf32(val.z); u.w = f2tf32(val.w);
            *reinterpret_cast<uint4*>(&Bs[row * 72 + q]) = u;
        }
        __syncthreads();

        #pragma unroll
        for (int kk = 0; kk < 4; ++kk) {
            uint32_t a[2][4];
            #pragma unroll
            for (int mm = 0; mm < 2; ++mm) {
                const uint32_t* ap = &As[(wm * 32 + mm * 16 + r) * 36 + kk * 8 + c];
                a[mm][0] = ap[0];
                a[mm][1] = ap[8 * 36];
                a[mm][2] = ap[4];
                a[mm][3] = ap[8 * 36 + 4];
            }
            uint32_t bf[4][2];
            #pragma unroll
            for (int nn = 0; nn < 4; ++nn) {
                const uint32_t* bp = &Bs[(kk * 8 + c) * 72 + wn * 32 + nn * 8 + r];
                bf[nn][0] = bp[0];
                bf[nn][1] = bp[4 * 72];
            }
            #pragma unroll
            for (int mm = 0; mm < 2; ++mm)
                #pragma unroll
                for (int nn = 0; nn < 4; ++nn)
                    mma_tf32(acc[mm][nn], a[mm], bf[nn]);
        }
    }

    // Epilogue: tanh(acc + hidb) * v, reduce over this block's 64 columns
    const int bb = m0 >> 11;                    // BM=128 divides S=2048 -> one batch per block
    const float* hb = g_hidb + bb * H_ + n0;

    float hcol[8], vcol[8];
    #pragma unroll
    for (int nn = 0; nn < 4; ++nn)
        #pragma unroll
        for (int bit = 0; bit < 2; ++bit) {
            int col = wn * 32 + nn * 8 + c * 2 + bit;
            hcol[nn * 2 + bit] = hb[col];
            vcol[nn * 2 + bit] = __ldg(&v[n0 + col]);
        }

    #pragma unroll
    for (int mm = 0; mm < 2; ++mm) {
        float p0 = 0.0f, p1 = 0.0f;
        #pragma unroll
        for (int nn = 0; nn < 4; ++nn) {
            p0 += fast_tanh(acc[mm][nn][0] + hcol[nn * 2 + 0]) * vcol[nn * 2 + 0];
            p0 += fast_tanh(acc[mm][nn][1] + hcol[nn * 2 + 1]) * vcol[nn * 2 + 1];
            p1 += fast_tanh(acc[mm][nn][2] + hcol[nn * 2 + 0]) * vcol[nn * 2 + 0];
            p1 += fast_tanh(acc[mm][nn][3] + hcol[nn * 2 + 1]) * vcol[nn * 2 + 1];
        }
        // reduce across the 4 lanes sharing a row (lane%4 group)
        p0 += __shfl_xor_sync(0xffffffffu, p0, 1);
        p0 += __shfl_xor_sync(0xffffffffu, p0, 2);
        p1 += __shfl_xor_sync(0xffffffffu, p1, 1);
        p1 += __shfl_xor_sync(0xffffffffu, p1, 2);
        if (c == 0) {
            int rbase = m0 + wm * 32 + mm * 16 + r;
            atomicAdd(&g_logits[rbase], p0);
            atomicAdd(&g_logits[rbase + 8], p1);
        }
    }
}

// ---------------------------------------------------------------------------
// Kernel 3: softmax over S per batch row
__global__ __launch_bounds__(256) void softmax_kernel(float* __restrict__ out) {
    __shared__ float red[256];
    int b = blockIdx.x;
    int t = threadIdx.x;
    const float* lg = g_logits + b * S_;

    float m = -1e30f;
    for (int i = t; i < S_; i += 256) m = fmaxf(m, lg[i]);
    red[t] = m;
    __syncthreads();
    for (int s = 128; s > 0; s >>= 1) {
        if (t < s) red[t] = fmaxf(red[t], red[t + s]);
        __syncthreads();
    }
    m = red[0];
    __syncthreads();

    float sum = 0.0f;
    for (int i = t; i < S_; i += 256) sum += expf(lg[i] - m);
    red[t] = sum;
    __syncthreads();
    for (int s = 128; s > 0; s >>= 1) {
        if (t < s) red[t] += red[t + s];
        __syncthreads();
    }
    float inv = 1.0f / red[0];

    for (int i = t; i < S_; i += 256) out[b * S_ + i] = expf(lg[i] - m) * inv;
}

// ---------------------------------------------------------------------------
extern "C" void kernel_launch(void* const* d_in, const int* in_sizes, int n_in,
                              void* d_out, int out_size) {
    const float* hidden  = (const float*)d_in[0];   // (16, 1024)
    const float* enc     = (const float*)d_in[1];   // (16, 2048, 1024)
    const float* W_attn  = (const float*)d_in[2];   // (2048, 1024)
    const float* b_attn  = (const float*)d_in[3];   // (1024,)
    const float* v       = (const float*)d_in[4];   // (1024,)
    float* out = (float*)d_out;                     // (16, 2048)

    prep_kernel<<<dim3(4, 16), 256>>>(hidden, W_attn, b_attn);
    attn_gemm_kernel<<<dim3(H_ / BN, M_TOTAL / BM), 256>>>(enc, W_attn + H_ * H_, v);
    softmax_kernel<<<B_, 256>>>(out);
}

// round 3
// speedup vs baseline: 1.5309x; 1.5309x over previous
#include <cuda_runtime.h>
#include <cuda_fp16.h>
#include <stdint.h>

#define B_ 16
#define S_ 2048
#define H_ 1024
#define M_TOTAL (B_ * S_)   // 32768

#define BM 128
#define BN 64
#define BK 32
#define K_ITERS (H_ / BK)   // 32
#define NSTAGES 3

// Stage layout in words (uint32): A 128 rows x 20 words, B 64 rows x 20 words
#define ROW_W 20                       // 16 data words (32 halves) + 4 pad
#define A_WORDS (BM * ROW_W)           // 2560
#define B_WORDS (BN * ROW_W)           // 1280
#define STAGE_WORDS (A_WORDS + B_WORDS) // 3840

// Device scratch (static arrays only — no allocs allowed)
__device__ float g_hidb[B_ * H_];                 // hidden @ W1 + bias
__device__ float g_logits[M_TOTAL];               // attention logits
__device__ __align__(16) __half g_ench[(size_t)M_TOTAL * H_];  // enc in fp16 (64MB)
__device__ __align__(16) __half g_w2th[(size_t)H_ * H_];       // W2^T fp16 [n][k] (2MB)

// ---------------------------------------------------------------------------
#define CP_ASYNC16(dst, src) \
    asm volatile("cp.async.cg.shared.global [%0], [%1], 16;" :: "r"(dst), "l"(src))
#define CP_COMMIT() asm volatile("cp.async.commit_group;" ::: "memory")

__device__ __forceinline__ uint32_t smem_u32(const void* p) {
    uint32_t a;
    asm("{ .reg .u64 t; cvta.to.shared.u64 t, %1; cvt.u32.u64 %0, t; }" : "=r"(a) : "l"(p));
    return a;
}

// fp16 mma with fp32 accumulate
__device__ __forceinline__ void mma_f16(float* d, const uint32_t* a, const uint32_t* b) {
    asm volatile(
        "mma.sync.aligned.m16n8k16.row.col.f32.f16.f16.f32 "
        "{%0,%1,%2,%3}, {%4,%5,%6,%7}, {%8,%9}, {%0,%1,%2,%3};\n"
        : "+f"(d[0]), "+f"(d[1]), "+f"(d[2]), "+f"(d[3])
        : "r"(a[0]), "r"(a[1]), "r"(a[2]), "r"(a[3]), "r"(b[0]), "r"(b[1]));
}

// Eigen/XLA rational tanh, FMA-pipe only. |err| ~ 1e-7 on [-8, 8]. (proven in R1)
__device__ __forceinline__ float fast_tanh(float x) {
    x = fminf(fmaxf(x, -7.99881172f), 7.99881172f);
    float x2 = x * x;
    float p = -2.76076847742355e-16f;
    p = fmaf(p, x2, 2.00018790482477e-13f);
    p = fmaf(p, x2, -8.60467152213735e-11f);
    p = fmaf(p, x2, 5.12229709037114e-08f);
    p = fmaf(p, x2, 1.48572235717979e-05f);
    p = fmaf(p, x2, 6.37261928875436e-04f);
    p = fmaf(p, x2, 4.89352455891786e-03f);
    p = p * x;
    float q = 1.19825839466702e-06f;
    q = fmaf(q, x2, 1.18534705686654e-04f);
    q = fmaf(q, x2, 2.26843463243900e-03f);
    q = fmaf(q, x2, 4.89352518554385e-03f);
    float r = __uint_as_float(0x7EF127EAu - __float_as_uint(q));
    r = r * (2.0f - q * r);
    r = r * (2.0f - q * r);
    r = r * (2.0f - q * r);
    return p * r;
}

// ---------------------------------------------------------------------------
// Kernel 0a: convert enc fp32 -> fp16 (8 elements per thread)
__global__ __launch_bounds__(256) void conv_enc_kernel(const float* __restrict__ enc) {
    size_t i = ((size_t)blockIdx.x * 256 + threadIdx.x) * 8;
    float4 v0 = *reinterpret_cast<const float4*>(enc + i);
    float4 v1 = *reinterpret_cast<const float4*>(enc + i + 4);
    __half2 h0 = __floats2half2_rn(v0.x, v0.y);
    __half2 h1 = __floats2half2_rn(v0.z, v0.w);
    __half2 h2 = __floats2half2_rn(v1.x, v1.y);
    __half2 h3 = __floats2half2_rn(v1.z, v1.w);
    uint4 u;
    u.x = *reinterpret_cast<uint32_t*>(&h0);
    u.y = *reinterpret_cast<uint32_t*>(&h1);
    u.z = *reinterpret_cast<uint32_t*>(&h2);
    u.w = *reinterpret_cast<uint32_t*>(&h3);
    *reinterpret_cast<uint4*>(&g_ench[i]) = u;
}

// ---------------------------------------------------------------------------
// Kernel 0b: transpose W2 -> g_w2th[n][k] fp16, + zero logits/hidb scratch
// grid (32, 32), block (32, 8)
__global__ __launch_bounds__(256) void conv_w2t_kernel(const float* __restrict__ W_attn) {
    __shared__ float tile[32][33];
    int bx = blockIdx.x, by = blockIdx.y;
    int tx = threadIdx.x, ty = threadIdx.y;
    int n = bx * 32 + tx;
    #pragma unroll
    for (int j = 0; j < 32; j += 8)
        tile[ty + j][tx] = W_attn[(size_t)(H_ + by * 32 + ty + j) * H_ + n];
    __syncthreads();
    int k = by * 32 + tx;
    #pragma unroll
    for (int j = 0; j < 32; j += 8)
        g_w2th[(size_t)(bx * 32 + ty + j) * H_ + k] = __float2half_rn(tile[tx][ty + j]);

    int bid = by * 32 + bx;
    int t = ty * 32 + tx;
    if (bid < 64) {
        g_logits[bid * 512 + t] = 0.0f;
        g_logits[bid * 512 + t + 256] = 0.0f;
    } else if (bid < 128) {
        g_hidb[(bid - 64) * 256 + t] = 0.0f;
    }
}

// ---------------------------------------------------------------------------
// Kernel 1: g_hidb[b][n] += partial(hidden @ W1) + bias (k-split, W1 read once)
// grid (4, 16): x = 256-col chunk, y = 64-row k chunk. fp32 exact.
__global__ __launch_bounds__(256) void prep_kernel(
    const float* __restrict__ hidden,
    const float* __restrict__ W_attn,
    const float* __restrict__ b_attn)
{
    __shared__ float sh[16][64];
    int n = blockIdx.x * 256 + threadIdx.x;
    int k0 = blockIdx.y * 64;
    for (int i = threadIdx.x; i < 16 * 64; i += 256)
        sh[i >> 6][i & 63] = hidden[(i >> 6) * H_ + k0 + (i & 63)];
    __syncthreads();

    float acc[16];
    float bias = (blockIdx.y == 0) ? b_attn[n] : 0.0f;
    #pragma unroll
    for (int b = 0; b < 16; ++b) acc[b] = bias;

    #pragma unroll 8
    for (int k = 0; k < 64; ++k) {
        float w = W_attn[(size_t)(k0 + k) * H_ + n];
        #pragma unroll
        for (int b = 0; b < 16; ++b) acc[b] = fmaf(sh[b][k], w, acc[b]);
    }
    #pragma unroll
    for (int b = 0; b < 16; ++b) atomicAdd(&g_hidb[b * H_ + n], acc[b]);
}

// ---------------------------------------------------------------------------
// Kernel 2: fp16 mma.sync GEMM (enc @ W2) + fused tanh(.+hidb) dot v epilogue
// grid (16 n-tiles, 256 m-tiles), 256 threads = 8 warps (4m x 2n), warp 32x32
__device__ __forceinline__ void load_stage(uint32_t a_base, uint32_t b_base,
                                           int m0, int n0, int kt, int tid)
{
    // A: 128 rows x 2 chunks-of-16B-pairs; each row = 4 x 16B at word offsets 0,4,8,12
    #pragma unroll
    for (int p = 0; p < 2; ++p) {
        int idx = p * 256 + tid;
        int row = idx >> 2;
        int q = (idx & 3) * 4;          // word offset within row
        CP_ASYNC16(a_base + (uint32_t)(row * ROW_W + q) * 4u,
                   &g_ench[(size_t)(m0 + row) * H_ + kt + 2 * q]);
    }
    // B: 64 rows x 4 chunks
    {
        int row = tid >> 2;
        int q = (tid & 3) * 4;
        CP_ASYNC16(b_base + (uint32_t)(row * ROW_W + q) * 4u,
                   &g_w2th[(size_t)(n0 + row) * H_ + kt + 2 * q]);
    }
    CP_COMMIT();
}

__global__ __launch_bounds__(256, 2) void attn_gemm_kernel(
    const float* __restrict__ v)
{
    __shared__ __align__(16) uint32_t sh[NSTAGES * STAGE_WORDS];
    __shared__ float sh_hb[BN];
    __shared__ float sh_v[BN];

    const int tid = threadIdx.x;
    const int lane = tid & 31;
    const int warp = tid >> 5;
    const int wm = warp >> 1;   // 0..3
    const int wn = warp & 1;    // 0..1
    const int r = lane >> 2;    // 0..7
    const int c = lane & 3;     // 0..3
    const int m0 = blockIdx.y * BM;
    const int n0 = blockIdx.x * BN;
    const int batch = m0 >> 11;

    const uint32_t smem_base = smem_u32(sh);

    if (tid < BN) {
        sh_hb[tid] = g_hidb[batch * H_ + n0 + tid];
        sh_v[tid]  = v[n0 + tid];
    }

    // prologue: stages 0,1
    load_stage(smem_base, smem_base + A_WORDS * 4, m0, n0, 0, tid);
    load_stage(smem_base + STAGE_WORDS * 4, smem_base + (STAGE_WORDS + A_WORDS) * 4,
               m0, n0, BK, tid);

    float acc[2][4][4];
    #pragma unroll
    for (int mm = 0; mm < 2; ++mm)
        #pragma unroll
        for (int nn = 0; nn < 4; ++nn)
            #pragma unroll
            for (int i = 0; i < 4; ++i) acc[mm][nn][i] = 0.0f;

    for (int i = 0; i < K_ITERS; ++i) {
        if (i == K_ITERS - 1) asm volatile("cp.async.wait_group 0;" ::: "memory");
        else                  asm volatile("cp.async.wait_group 1;" ::: "memory");
        __syncthreads();

        if (i + 2 < K_ITERS) {
            int ts = (i + 2) % NSTAGES;
            load_stage(smem_base + (uint32_t)(ts * STAGE_WORDS) * 4u,
                       smem_base + (uint32_t)(ts * STAGE_WORDS + A_WORDS) * 4u,
                       m0, n0, (i + 2) * BK, tid);
        }

        const uint32_t* As = sh + (i % NSTAGES) * STAGE_WORDS;
        const uint32_t* Bs = As + A_WORDS;

        #pragma unroll
        for (int ks = 0; ks < 2; ++ks) {
            uint32_t a[2][4];
            #pragma unroll
            for (int mm = 0; mm < 2; ++mm) {
                const uint32_t* ap = &As[(wm * 32 + mm * 16 + r) * ROW_W + ks * 8 + c];
                a[mm][0] = ap[0];
                a[mm][1] = ap[8 * ROW_W];
                a[mm][2] = ap[4];
                a[mm][3] = ap[8 * ROW_W + 4];
            }
            uint32_t bf[4][2];
            #pragma unroll
            for (int nn = 0; nn < 4; ++nn) {
                const uint32_t* bp = &Bs[(wn * 32 + nn * 8 + r) * ROW_W + ks * 8 + c];
                bf[nn][0] = bp[0];
                bf[nn][1] = bp[4];
            }
            #pragma unroll
            for (int mm = 0; mm < 2; ++mm)
                #pragma unroll
                for (int nn = 0; nn < 4; ++nn)
                    mma_f16(acc[mm][nn], a[mm], bf[nn]);
        }
        __syncthreads();
    }

    // Epilogue: tanh(acc + hidb) * v, reduce, atomicAdd into logits
    float hcol[8], vcol[8];
    #pragma unroll
    for (int nn = 0; nn < 4; ++nn)
        #pragma unroll
        for (int bit = 0; bit < 2; ++bit) {
            int col = wn * 32 + nn * 8 + c * 2 + bit;
            hcol[nn * 2 + bit] = sh_hb[col];
            vcol[nn * 2 + bit] = sh_v[col];
        }

    #pragma unroll
    for (int mm = 0; mm < 2; ++mm) {
        float p0 = 0.0f, p1 = 0.0f;
        #pragma unroll
        for (int nn = 0; nn < 4; ++nn) {
            p0 += fast_tanh(acc[mm][nn][0] + hcol[nn * 2 + 0]) * vcol[nn * 2 + 0];
            p0 += fast_tanh(acc[mm][nn][1] + hcol[nn * 2 + 1]) * vcol[nn * 2 + 1];
            p1 += fast_tanh(acc[mm][nn][2] + hcol[nn * 2 + 0]) * vcol[nn * 2 + 0];
            p1 += fast_tanh(acc[mm][nn][3] + hcol[nn * 2 + 1]) * vcol[nn * 2 + 1];
        }
        p0 += __shfl_xor_sync(0xffffffffu, p0, 1);
        p0 += __shfl_xor_sync(0xffffffffu, p0, 2);
        p1 += __shfl_xor_sync(0xffffffffu, p1, 1);
        p1 += __shfl_xor_sync(0xffffffffu, p1, 2);
        if (c == 0) {
            int rbase = m0 + wm * 32 + mm * 16 + r;
            atomicAdd(&g_logits[rbase], p0);
            atomicAdd(&g_logits[rbase + 8], p1);
        }
    }
}

// ---------------------------------------------------------------------------
// Kernel 3: softmax over S per batch row
__global__ __launch_bounds__(256) void softmax_kernel(float* __restrict__ out) {
    __shared__ float red[256];
    int b = blockIdx.x;
    int t = threadIdx.x;
    const float* lg = g_logits + b * S_;

    float m = -1e30f;
    for (int i = t; i < S_; i += 256) m = fmaxf(m, lg[i]);
    red[t] = m;
    __syncthreads();
    for (int s = 128; s > 0; s >>= 1) {
        if (t < s) red[t] = fmaxf(red[t], red[t + s]);
        __syncthreads();
    }
    m = red[0];
    __syncthreads();

    float sum = 0.0f;
    for (int i = t; i < S_; i += 256) sum += expf(lg[i] - m);
    red[t] = sum;
    __syncthreads();
    for (int s = 128; s > 0; s >>= 1) {
        if (t < s) red[t] += red[t + s];
        __syncthreads();
    }
    float inv = 1.0f / red[0];

    for (int i = t; i < S_; i += 256) out[b * S_ + i] = expf(lg[i] - m) * inv;
}

// ---------------------------------------------------------------------------
extern "C" void kernel_launch(void* const* d_in, const int* in_sizes, int n_in,
                              void* d_out, int out_size) {
    const float* hidden  = (const float*)d_in[0];   // (16, 1024)
    const float* enc     = (const float*)d_in[1];   // (16, 2048, 1024)
    const float* W_attn  = (const float*)d_in[2];   // (2048, 1024)
    const float* b_attn  = (const float*)d_in[3];   // (1024,)
    const float* v       = (const float*)d_in[4];   // (1024,)
    float* out = (float*)d_out;                     // (16, 2048)

    conv_enc_kernel<<<(size_t)M_TOTAL * H_ / 8 / 256, 256>>>(enc);
    conv_w2t_kernel<<<dim3(32, 32), dim3(32, 8)>>>(W_attn);
    prep_kernel<<<dim3(4, 16), 256>>>(hidden, W_attn, b_attn);
    attn_gemm_kernel<<<dim3(H_ / BN, M_TOTAL / BM), 256>>>(v);
    softmax_kernel<<<B_, 256>>>(out);
}

// round 5
// speedup vs baseline: 2.3374x; 1.5268x over previous
#include <cuda_runtime.h>
#include <cuda_fp16.h>
#include <stdint.h>

#define B_ 16
#define S_ 2048
#define H_ 1024
#define M_TOTAL (B_ * S_)   // 32768

#define BM 128
#define BN 128
#define BK 32
#define K_ITERS (H_ / BK)   // 32
#define NSTAGES 4

// Tile rows are 32 halves = 64B = 4 chunks of 16B, XOR-swizzled
#define A_BYTES (BM * 64)              // 8192
#define B_BYTES (BN * 64)              // 8192
#define STAGE_BYTES (A_BYTES + B_BYTES) // 16384
#define SMEM_TOTAL (NSTAGES * STAGE_BYTES + 1024)  // 66560

// Device scratch (static arrays only — no allocs allowed)
__device__ float g_hidb[B_ * H_];
__device__ float g_logits[M_TOTAL];
__device__ __align__(16) __half g_ench[(size_t)M_TOTAL * H_];  // enc fp16 (64MB)
__device__ __align__(16) __half g_w2th[(size_t)H_ * H_];       // W2^T fp16 [n][k]

// ---------------------------------------------------------------------------
#define CP_ASYNC16(dst, src) \
    asm volatile("cp.async.cg.shared.global [%0], [%1], 16;" :: "r"(dst), "l"(src))
#define CP_COMMIT() asm volatile("cp.async.commit_group;" ::: "memory")

__device__ __forceinline__ uint32_t smem_u32(const void* p) {
    uint32_t a;
    asm("{ .reg .u64 t; cvta.to.shared.u64 t, %1; cvt.u32.u64 %0, t; }" : "=r"(a) : "l"(p));
    return a;
}

__device__ __forceinline__ void ldmx4(uint32_t* r, uint32_t addr) {
    asm volatile("ldmatrix.sync.aligned.m8n8.x4.shared.b16 {%0,%1,%2,%3}, [%4];"
                 : "=r"(r[0]), "=r"(r[1]), "=r"(r[2]), "=r"(r[3]) : "r"(addr));
}

__device__ __forceinline__ void mma_f16(float* d, const uint32_t* a, const uint32_t* b) {
    asm volatile(
        "mma.sync.aligned.m16n8k16.row.col.f32.f16.f16.f32 "
        "{%0,%1,%2,%3}, {%4,%5,%6,%7}, {%8,%9}, {%0,%1,%2,%3};\n"
        : "+f"(d[0]), "+f"(d[1]), "+f"(d[2]), "+f"(d[3])
        : "r"(a[0]), "r"(a[1]), "r"(a[2]), "r"(a[3]), "r"(b[0]), "r"(b[1]));
}

// Eigen/XLA rational tanh, FMA-pipe only. |err| ~ 1e-7 on [-8, 8].
__device__ __forceinline__ float fast_tanh(float x) {
    x = fminf(fmaxf(x, -7.99881172f), 7.99881172f);
    float x2 = x * x;
    float p = -2.76076847742355e-16f;
    p = fmaf(p, x2, 2.00018790482477e-13f);
    p = fmaf(p, x2, -8.60467152213735e-11f);
    p = fmaf(p, x2, 5.12229709037114e-08f);
    p = fmaf(p, x2, 1.48572235717979e-05f);
    p = fmaf(p, x2, 6.37261928875436e-04f);
    p = fmaf(p, x2, 4.89352455891786e-03f);
    p = p * x;
    float q = 1.19825839466702e-06f;
    q = fmaf(q, x2, 1.18534705686654e-04f);
    q = fmaf(q, x2, 2.26843463243900e-03f);
    q = fmaf(q, x2, 4.89352518554385e-03f);
    float r = __uint_as_float(0x7EF127EAu - __float_as_uint(q));
    r = r * (2.0f - q * r);
    r = r * (2.0f - q * r);
    r = r * (2.0f - q * r);
    return p * r;
}

// ---------------------------------------------------------------------------
// Kernel 0a: convert enc fp32 -> fp16 (8 elements per thread)
__global__ __launch_bounds__(256) void conv_enc_kernel(const float* __restrict__ enc) {
    size_t i = ((size_t)blockIdx.x * 256 + threadIdx.x) * 8;
    float4 v0 = *reinterpret_cast<const float4*>(enc + i);
    float4 v1 = *reinterpret_cast<const float4*>(enc + i + 4);
    __half2 h0 = __floats2half2_rn(v0.x, v0.y);
    __half2 h1 = __floats2half2_rn(v0.z, v0.w);
    __half2 h2 = __floats2half2_rn(v1.x, v1.y);
    __half2 h3 = __floats2half2_rn(v1.z, v1.w);
    uint4 u;
    u.x = *reinterpret_cast<uint32_t*>(&h0);
    u.y = *reinterpret_cast<uint32_t*>(&h1);
    u.z = *reinterpret_cast<uint32_t*>(&h2);
    u.w = *reinterpret_cast<uint32_t*>(&h3);
    *reinterpret_cast<uint4*>(&g_ench[i]) = u;
}

// ---------------------------------------------------------------------------
// Kernel 0b: transpose W2 -> g_w2th[n][k] fp16, + zero logits/hidb scratch
__global__ __launch_bounds__(256) void conv_w2t_kernel(const float* __restrict__ W_attn) {
    __shared__ float tile[32][33];
    int bx = blockIdx.x, by = blockIdx.y;
    int tx = threadIdx.x, ty = threadIdx.y;
    int n = bx * 32 + tx;
    #pragma unroll
    for (int j = 0; j < 32; j += 8)
        tile[ty + j][tx] = W_attn[(size_t)(H_ + by * 32 + ty + j) * H_ + n];
    __syncthreads();
    int k = by * 32 + tx;
    #pragma unroll
    for (int j = 0; j < 32; j += 8)
        g_w2th[(size_t)(bx * 32 + ty + j) * H_ + k] = __float2half_rn(tile[tx][ty + j]);

    int bid = by * 32 + bx;
    int t = ty * 32 + tx;
    if (bid < 64) {
        g_logits[bid * 512 + t] = 0.0f;
        g_logits[bid * 512 + t + 256] = 0.0f;
    } else if (bid < 128) {
        g_hidb[(bid - 64) * 256 + t] = 0.0f;
    }
}

// ---------------------------------------------------------------------------
// Kernel 1: g_hidb[b][n] += partial(hidden @ W1) + bias (k-split, W1 read once)
__global__ __launch_bounds__(256) void prep_kernel(
    const float* __restrict__ hidden,
    const float* __restrict__ W_attn,
    const float* __restrict__ b_attn)
{
    __shared__ float sh[16][64];
    int n = blockIdx.x * 256 + threadIdx.x;
    int k0 = blockIdx.y * 64;
    for (int i = threadIdx.x; i < 16 * 64; i += 256)
        sh[i >> 6][i & 63] = hidden[(i >> 6) * H_ + k0 + (i & 63)];
    __syncthreads();

    float acc[16];
    float bias = (blockIdx.y == 0) ? b_attn[n] : 0.0f;
    #pragma unroll
    for (int b = 0; b < 16; ++b) acc[b] = bias;

    #pragma unroll 8
    for (int k = 0; k < 64; ++k) {
        float w = W_attn[(size_t)(k0 + k) * H_ + n];
        #pragma unroll
        for (int b = 0; b < 16; ++b) acc[b] = fmaf(sh[b][k], w, acc[b]);
    }
    #pragma unroll
    for (int b = 0; b < 16; ++b) atomicAdd(&g_hidb[b * H_ + n], acc[b]);
}

// ---------------------------------------------------------------------------
// Kernel 2: fp16 mma GEMM (enc @ W2) via ldmatrix + 4-stage cp.async pipeline
// grid (8 n-tiles, 256 m-tiles), 256 threads = 8 warps (2m x 4n), warp 64x32
__device__ __forceinline__ void load_stage(uint32_t stage_base,
                                           int m0, int n0, int kt, int tid)
{
    // A: 128 rows x 4 chunks of 16B (swizzled)
    #pragma unroll
    for (int p = 0; p < 2; ++p) {
        int cid = p * 256 + tid;
        int row = cid >> 2, c = cid & 3;
        uint32_t off = (uint32_t)row * 64u + (uint32_t)((c ^ ((row >> 1) & 3)) << 4);
        CP_ASYNC16(stage_base + off,
                   &g_ench[(size_t)(m0 + row) * H_ + kt + c * 8]);
    }
    // B: 128 rows x 4 chunks
    #pragma unroll
    for (int p = 0; p < 2; ++p) {
        int cid = p * 256 + tid;
        int row = cid >> 2, c = cid & 3;
        uint32_t off = (uint32_t)row * 64u + (uint32_t)((c ^ ((row >> 1) & 3)) << 4);
        CP_ASYNC16(stage_base + A_BYTES + off,
                   &g_w2th[(size_t)(n0 + row) * H_ + kt + c * 8]);
    }
    CP_COMMIT();
}

__global__ __launch_bounds__(256, 2) void attn_gemm_kernel(
    const float* __restrict__ v)
{
    extern __shared__ char smem[];
    float* sh_hb = (float*)(smem + NSTAGES * STAGE_BYTES);
    float* sh_v  = sh_hb + BN;
    const uint32_t smem_base = smem_u32(smem);

    const int tid = threadIdx.x;
    const int lane = tid & 31;
    const int warp = tid >> 5;
    const int wm = warp >> 2;       // 0..1 (64-row slab)
    const int wn = warp & 3;        // 0..3 (32-col slab)
    const int r = lane >> 2;        // 0..7
    const int c = lane & 3;         // 0..3
    const int i8 = lane & 7;
    const int sub = lane >> 3;      // 0..3 (ldmatrix octet)
    const uint32_t fxor = (uint32_t)((i8 >> 1) & 3);

    const int m0 = blockIdx.y * BM;
    const int n0 = blockIdx.x * BN;
    const int batch = m0 >> 11;

    // ldmatrix per-thread row/chunk components
    const uint32_t a_row = (uint32_t)(wm * 64 + i8 + 8 * (sub & 1));
    const uint32_t a_csub = (uint32_t)(sub >> 1);
    const uint32_t b_row = (uint32_t)(wn * 32 + i8 + 8 * (sub >> 1));
    const uint32_t b_csub = (uint32_t)(sub & 1);

    if (tid < BN) {
        sh_hb[tid] = g_hidb[batch * H_ + n0 + tid];
        sh_v[tid]  = v[n0 + tid];
    }

    // prologue: stages 0,1,2
    #pragma unroll
    for (int s = 0; s < 3; ++s)
        load_stage(smem_base + s * STAGE_BYTES, m0, n0, s * BK, tid);

    float acc[2][4][4];
    #pragma unroll
    for (int mm = 0; mm < 2; ++mm)
        #pragma unroll
        for (int nn = 0; nn < 4; ++nn)
            #pragma unroll
            for (int i = 0; i < 4; ++i) acc[mm][nn][i] = 0.0f;
    float acc2[2][4][4];
    #pragma unroll
    for (int mm = 0; mm < 2; ++mm)
        #pragma unroll
        for (int nn = 0; nn < 4; ++nn)
            #pragma unroll
            for (int i = 0; i < 4; ++i) acc2[mm][nn][i] = 0.0f;

    for (int i = 0; i < K_ITERS; ++i) {
        if (i < K_ITERS - 2)      asm volatile("cp.async.wait_group 2;" ::: "memory");
        else if (i == K_ITERS - 2) asm volatile("cp.async.wait_group 1;" ::: "memory");
        else                       asm volatile("cp.async.wait_group 0;" ::: "memory");
        __syncthreads();

        if (i + 3 < K_ITERS)
            load_stage(smem_base + ((i + 3) % NSTAGES) * STAGE_BYTES,
                       m0, n0, (i + 3) * BK, tid);

        const uint32_t sa = smem_base + (i % NSTAGES) * STAGE_BYTES;
        const uint32_t sb = sa + A_BYTES;

        #pragma unroll
        for (int ks = 0; ks < 2; ++ks) {
            uint32_t af[4][4];
            #pragma unroll
            for (int mm = 0; mm < 4; ++mm) {
                uint32_t addr = sa + (a_row + mm * 16) * 64u
                              + (((ks * 2 + a_csub) ^ fxor) << 4);
                ldmx4(af[mm], addr);
            }
            uint32_t bf[4][2];
            #pragma unroll
            for (int nnp = 0; nnp < 2; ++nnp) {
                uint32_t tmp[4];
                uint32_t addr = sb + (b_row + nnp * 16) * 64u
                              + (((ks * 2 + b_csub) ^ fxor) << 4);
                ldmx4(tmp, addr);
                bf[nnp * 2 + 0][0] = tmp[0];
                bf[nnp * 2 + 0][1] = tmp[1];
                bf[nnp * 2 + 1][0] = tmp[2];
                bf[nnp * 2 + 1][1] = tmp[3];
            }
            #pragma unroll
            for (int mm = 0; mm < 4; ++mm) {
                float (*ac)[4] = (mm < 2) ? acc[mm] : acc2[mm - 2];
                #pragma unroll
                for (int nn = 0; nn < 4; ++nn)
                    mma_f16(ac[nn], af[mm], bf[nn]);
            }
        }
        __syncthreads();
    }

    // Epilogue: tanh(acc + hidb) * v, reduce over 4 lanes, atomicAdd
    float hcol[8], vcol[8];
    #pragma unroll
    for (int nn = 0; nn < 4; ++nn)
        #pragma unroll
        for (int bit = 0; bit < 2; ++bit) {
            int col = wn * 32 + nn * 8 + c * 2 + bit;
            hcol[nn * 2 + bit] = sh_hb[col];
            vcol[nn * 2 + bit] = sh_v[col];
        }

    #pragma unroll
    for (int mm = 0; mm < 4; ++mm) {
        float (*ac)[4] = (mm < 2) ? acc[mm] : acc2[mm - 2];
        float p0 = 0.0f, p1 = 0.0f;
        #pragma unroll
        for (int nn = 0; nn < 4; ++nn) {
            p0 += fast_tanh(ac[nn][0] + hcol[nn * 2 + 0]) * vcol[nn * 2 + 0];
            p0 += fast_tanh(ac[nn][1] + hcol[nn * 2 + 1]) * vcol[nn * 2 + 1];
            p1 += fast_tanh(ac[nn][2] + hcol[nn * 2 + 0]) * vcol[nn * 2 + 0];
            p1 += fast_tanh(ac[nn][3] + hcol[nn * 2 + 1]) * vcol[nn * 2 + 1];
        }
        p0 += __shfl_xor_sync(0xffffffffu, p0, 1);
        p0 += __shfl_xor_sync(0xffffffffu, p0, 2);
        p1 += __shfl_xor_sync(0xffffffffu, p1, 1);
        p1 += __shfl_xor_sync(0xffffffffu, p1, 2);
        if (c == 0) {
            int rbase = m0 + wm * 64 + mm * 16 + r;
            atomicAdd(&g_logits[rbase], p0);
            atomicAdd(&g_logits[rbase + 8], p1);
        }
    }
}

// ---------------------------------------------------------------------------
// Kernel 3: softmax over S per batch row
__global__ __launch_bounds__(256) void softmax_kernel(float* __restrict__ out) {
    __shared__ float red[256];
    int b = blockIdx.x;
    int t = threadIdx.x;
    const float* lg = g_logits + b * S_;

    float m = -1e30f;
    for (int i = t; i < S_; i += 256) m = fmaxf(m, lg[i]);
    red[t] = m;
    __syncthreads();
    for (int s = 128; s > 0; s >>= 1) {
        if (t < s) red[t] = fmaxf(red[t], red[t + s]);
        __syncthreads();
    }
    m = red[0];
    __syncthreads();

    float sum = 0.0f;
    for (int i = t; i < S_; i += 256) sum += expf(lg[i] - m);
    red[t] = sum;
    __syncthreads();
    for (int s = 128; s > 0; s >>= 1) {
        if (t < s) red[t] += red[t + s];
        __syncthreads();
    }
    float inv = 1.0f / red[0];

    for (int i = t; i < S_; i += 256) out[b * S_ + i] = expf(lg[i] - m) * inv;
}

// ---------------------------------------------------------------------------
extern "C" void kernel_launch(void* const* d_in, const int* in_sizes, int n_in,
                              void* d_out, int out_size) {
    const float* hidden  = (const float*)d_in[0];   // (16, 1024)
    const float* enc     = (const float*)d_in[1];   // (16, 2048, 1024)
    const float* W_attn  = (const float*)d_in[2];   // (2048, 1024)
    const float* b_attn  = (const float*)d_in[3];   // (1024,)
    const float* v       = (const float*)d_in[4];   // (1024,)
    float* out = (float*)d_out;                     // (16, 2048)

    cudaFuncSetAttribute(attn_gemm_kernel,
                         cudaFuncAttributeMaxDynamicSharedMemorySize, SMEM_TOTAL);

    conv_enc_kernel<<<(size_t)M_TOTAL * H_ / 8 / 256, 256>>>(enc);
    conv_w2t_kernel<<<dim3(32, 32), dim3(32, 8)>>>(W_attn);
    prep_kernel<<<dim3(4, 16), 256>>>(hidden, W_attn, b_attn);
    attn_gemm_kernel<<<dim3(H_ / BN, M_TOTAL / BM), 256, SMEM_TOTAL>>>(v);
    softmax_kernel<<<B_, 256>>>(out);
}

// round 6
// speedup vs baseline: 2.6049x; 1.1144x over previous
#include <cuda_runtime.h>
#include <cuda_fp16.h>
#include <stdint.h>

#define B_ 16
#define S_ 2048
#define H_ 1024
#define M_TOTAL (B_ * S_)   // 32768

#define BM 128
#define BN 128
#define BK 64
#define K_ITERS (H_ / BK)   // 16
#define NSTAGES 3

// Tile rows are 64 halves = 128B = 8 chunks of 16B, XOR-swizzled (c ^ (row&7))
#define A_BYTES (BM * 128)               // 16384
#define STAGE_BYTES (2 * A_BYTES)        // 32768
#define SMEM_TOTAL (NSTAGES * STAGE_BYTES + 1024)  // 99328

// Device scratch (static arrays only — no allocs allowed)
__device__ float g_hidb[B_ * H_];
__device__ float g_logits[M_TOTAL];
__device__ __align__(16) __half g_ench[(size_t)M_TOTAL * H_];  // enc fp16 (64MB)
__device__ __align__(16) __half g_w2th[(size_t)H_ * H_];       // W2^T fp16 [n][k]

// ---------------------------------------------------------------------------
#define CP_ASYNC16(dst, src) \
    asm volatile("cp.async.cg.shared.global [%0], [%1], 16;" :: "r"(dst), "l"(src))
#define CP_COMMIT() asm volatile("cp.async.commit_group;" ::: "memory")

__device__ __forceinline__ uint32_t smem_u32(const void* p) {
    uint32_t a;
    asm("{ .reg .u64 t; cvta.to.shared.u64 t, %1; cvt.u32.u64 %0, t; }" : "=r"(a) : "l"(p));
    return a;
}

__device__ __forceinline__ void ldmx4(uint32_t* r, uint32_t addr) {
    asm volatile("ldmatrix.sync.aligned.m8n8.x4.shared.b16 {%0,%1,%2,%3}, [%4];"
                 : "=r"(r[0]), "=r"(r[1]), "=r"(r[2]), "=r"(r[3]) : "r"(addr));
}

__device__ __forceinline__ void mma_f16(float* d, const uint32_t* a, const uint32_t* b) {
    asm volatile(
        "mma.sync.aligned.m16n8k16.row.col.f32.f16.f16.f32 "
        "{%0,%1,%2,%3}, {%4,%5,%6,%7}, {%8,%9}, {%0,%1,%2,%3};\n"
        : "+f"(d[0]), "+f"(d[1]), "+f"(d[2]), "+f"(d[3])
        : "r"(a[0]), "r"(a[1]), "r"(a[2]), "r"(a[3]), "r"(b[0]), "r"(b[1]));
}

// Eigen/XLA rational tanh, FMA-pipe only. |err| ~ 1e-7 on [-8, 8].
__device__ __forceinline__ float fast_tanh(float x) {
    x = fminf(fmaxf(x, -7.99881172f), 7.99881172f);
    float x2 = x * x;
    float p = -2.76076847742355e-16f;
    p = fmaf(p, x2, 2.00018790482477e-13f);
    p = fmaf(p, x2, -8.60467152213735e-11f);
    p = fmaf(p, x2, 5.12229709037114e-08f);
    p = fmaf(p, x2, 1.48572235717979e-05f);
    p = fmaf(p, x2, 6.37261928875436e-04f);
    p = fmaf(p, x2, 4.89352455891786e-03f);
    p = p * x;
    float q = 1.19825839466702e-06f;
    q = fmaf(q, x2, 1.18534705686654e-04f);
    q = fmaf(q, x2, 2.26843463243900e-03f);
    q = fmaf(q, x2, 4.89352518554385e-03f);
    float r = __uint_as_float(0x7EF127EAu - __float_as_uint(q));
    r = r * (2.0f - q * r);
    r = r * (2.0f - q * r);
    r = r * (2.0f - q * r);
    return p * r;
}

// ---------------------------------------------------------------------------
// Kernel 0a: convert enc fp32 -> fp16 (8 elements per thread)
__global__ __launch_bounds__(256) void conv_enc_kernel(const float* __restrict__ enc) {
    size_t i = ((size_t)blockIdx.x * 256 + threadIdx.x) * 8;
    float4 v0 = *reinterpret_cast<const float4*>(enc + i);
    float4 v1 = *reinterpret_cast<const float4*>(enc + i + 4);
    __half2 h0 = __floats2half2_rn(v0.x, v0.y);
    __half2 h1 = __floats2half2_rn(v0.z, v0.w);
    __half2 h2 = __floats2half2_rn(v1.x, v1.y);
    __half2 h3 = __floats2half2_rn(v1.z, v1.w);
    uint4 u;
    u.x = *reinterpret_cast<uint32_t*>(&h0);
    u.y = *reinterpret_cast<uint32_t*>(&h1);
    u.z = *reinterpret_cast<uint32_t*>(&h2);
    u.w = *reinterpret_cast<uint32_t*>(&h3);
    *reinterpret_cast<uint4*>(&g_ench[i]) = u;
}

// ---------------------------------------------------------------------------
// Kernel 0b: transpose W2 -> g_w2th[n][k] fp16, + zero logits/hidb scratch
__global__ __launch_bounds__(256) void conv_w2t_kernel(const float* __restrict__ W_attn) {
    __shared__ float tile[32][33];
    int bx = blockIdx.x, by = blockIdx.y;
    int tx = threadIdx.x, ty = threadIdx.y;
    int n = bx * 32 + tx;
    #pragma unroll
    for (int j = 0; j < 32; j += 8)
        tile[ty + j][tx] = W_attn[(size_t)(H_ + by * 32 + ty + j) * H_ + n];
    __syncthreads();
    int k = by * 32 + tx;
    #pragma unroll
    for (int j = 0; j < 32; j += 8)
        g_w2th[(size_t)(bx * 32 + ty + j) * H_ + k] = __float2half_rn(tile[tx][ty + j]);

    int bid = by * 32 + bx;
    int t = ty * 32 + tx;
    if (bid < 64) {
        g_logits[bid * 512 + t] = 0.0f;
        g_logits[bid * 512 + t + 256] = 0.0f;
    } else if (bid < 128) {
        g_hidb[(bid - 64) * 256 + t] = 0.0f;
    }
}

// ---------------------------------------------------------------------------
// Kernel 1: g_hidb[b][n] += partial(hidden @ W1) + bias (k-split, W1 read once)
__global__ __launch_bounds__(256) void prep_kernel(
    const float* __restrict__ hidden,
    const float* __restrict__ W_attn,
    const float* __restrict__ b_attn)
{
    __shared__ float sh[16][64];
    int n = blockIdx.x * 256 + threadIdx.x;
    int k0 = blockIdx.y * 64;
    for (int i = threadIdx.x; i < 16 * 64; i += 256)
        sh[i >> 6][i & 63] = hidden[(i >> 6) * H_ + k0 + (i & 63)];
    __syncthreads();

    float acc[16];
    float bias = (blockIdx.y == 0) ? b_attn[n] : 0.0f;
    #pragma unroll
    for (int b = 0; b < 16; ++b) acc[b] = bias;

    #pragma unroll 8
    for (int k = 0; k < 64; ++k) {
        float w = W_attn[(size_t)(k0 + k) * H_ + n];
        #pragma unroll
        for (int b = 0; b < 16; ++b) acc[b] = fmaf(sh[b][k], w, acc[b]);
    }
    #pragma unroll
    for (int b = 0; b < 16; ++b) atomicAdd(&g_hidb[b * H_ + n], acc[b]);
}

// ---------------------------------------------------------------------------
// Kernel 2: fp16 mma GEMM, BK=64, 3-stage cp.async ring, 1 barrier/iter
// grid (8 n-tiles, 256 m-tiles), 256 threads = 8 warps (2m x 4n), warp 64x32
__global__ __launch_bounds__(256, 2) void attn_gemm_kernel(
    const float* __restrict__ v)
{
    extern __shared__ char smem[];
    float* sh_hb = (float*)(smem + NSTAGES * STAGE_BYTES);
    float* sh_v  = sh_hb + BN;
    const uint32_t smem_base = smem_u32(smem);

    const int tid = threadIdx.x;
    const int lane = tid & 31;
    const int warp = tid >> 5;
    const int wm = warp >> 2;       // 0..1 (64-row slab)
    const int wn = warp & 3;        // 0..3 (32-col slab)
    const int r = lane >> 2;        // 0..7
    const int c = lane & 3;         // 0..3
    const int i8 = lane & 7;
    const int sub = lane >> 3;      // 0..3 (ldmatrix octet)

    const int m0 = blockIdx.y * BM;
    const int n0 = blockIdx.x * BN;
    const int batch = m0 >> 11;

    // --- cp.async addressing (fully strength-reduced) ---
    // thread loads rows r0+32p (p=0..3), fixed chunk col cc, for both A and B
    const int r0 = tid >> 3;
    const int cc = tid & 7;
    const uint32_t st_off = (uint32_t)r0 * 128u + (uint32_t)((cc ^ (r0 & 7)) << 4);
    const __half* a_g = &g_ench[(size_t)(m0 + r0) * H_ + cc * 8];
    const __half* b_g = &g_w2th[(size_t)(n0 + r0) * H_ + cc * 8];

    // --- ldmatrix addressing ---
    const uint32_t a_row  = (uint32_t)(wm * 64 + i8 + 8 * (sub & 1));
    const uint32_t a_csub = (uint32_t)(sub >> 1);
    const uint32_t a_x    = a_row & 7;
    const uint32_t a_base = a_row * 128u;
    const uint32_t b_row  = (uint32_t)(wn * 32 + i8 + 8 * (sub >> 1));
    const uint32_t b_csub = (uint32_t)(sub & 1);
    const uint32_t b_x    = b_row & 7;
    const uint32_t b_base = A_BYTES + b_row * 128u;

    if (tid < BN) {
        sh_hb[tid] = g_hidb[batch * H_ + n0 + tid];
        sh_v[tid]  = v[n0 + tid];
    }

    // prologue: stages 0,1
    #pragma unroll
    for (int s = 0; s < 2; ++s) {
        uint32_t sb = smem_base + s * STAGE_BYTES;
        #pragma unroll
        for (int p = 0; p < 4; ++p) {
            CP_ASYNC16(sb + st_off + p * 4096u, a_g + (size_t)p * 32 * H_);
            CP_ASYNC16(sb + A_BYTES + st_off + p * 4096u, b_g + (size_t)p * 32 * H_);
        }
        CP_COMMIT();
        a_g += BK; b_g += BK;
    }

    float acc[2][4][4];
    float acc2[2][4][4];
    #pragma unroll
    for (int mm = 0; mm < 2; ++mm)
        #pragma unroll
        for (int nn = 0; nn < 4; ++nn)
            #pragma unroll
            for (int i = 0; i < 4; ++i) { acc[mm][nn][i] = 0.0f; acc2[mm][nn][i] = 0.0f; }

    for (int i = 0; i < K_ITERS; ++i) {
        if (i == K_ITERS - 1) asm volatile("cp.async.wait_group 0;" ::: "memory");
        else                  asm volatile("cp.async.wait_group 1;" ::: "memory");
        __syncthreads();

        // refill stage (i+2)%3 (== stage (i-1)%3, consumed before this barrier)
        if (i + 2 < K_ITERS) {
            uint32_t sbb = smem_base + ((i + 2) % NSTAGES) * STAGE_BYTES;
            #pragma unroll
            for (int p = 0; p < 4; ++p) {
                CP_ASYNC16(sbb + st_off + p * 4096u, a_g + (size_t)p * 32 * H_);
                CP_ASYNC16(sbb + A_BYTES + st_off + p * 4096u, b_g + (size_t)p * 32 * H_);
            }
            CP_COMMIT();
            a_g += BK; b_g += BK;
        }

        const uint32_t sa = smem_base + (i % NSTAGES) * STAGE_BYTES;

        #pragma unroll
        for (int ks = 0; ks < 4; ++ks) {
            uint32_t af[4][4];
            #pragma unroll
            for (int mm = 0; mm < 4; ++mm) {
                uint32_t addr = sa + a_base + mm * (16u * 128u)
                              + (((2 * ks + a_csub) ^ a_x) << 4);
                ldmx4(af[mm], addr);
            }
            uint32_t bf[4][2];
            #pragma unroll
            for (int nnp = 0; nnp < 2; ++nnp) {
                uint32_t tmp[4];
                uint32_t addr = sa + b_base + nnp * (16u * 128u)
                              + (((2 * ks + b_csub) ^ b_x) << 4);
                ldmx4(tmp, addr);
                bf[nnp * 2 + 0][0] = tmp[0];
                bf[nnp * 2 + 0][1] = tmp[1];
                bf[nnp * 2 + 1][0] = tmp[2];
                bf[nnp * 2 + 1][1] = tmp[3];
            }
            #pragma unroll
            for (int mm = 0; mm < 4; ++mm) {
                float (*ac)[4] = (mm < 2) ? acc[mm] : acc2[mm - 2];
                #pragma unroll
                for (int nn = 0; nn < 4; ++nn)
                    mma_f16(ac[nn], af[mm], bf[nn]);
            }
        }
    }

    // Epilogue: tanh(acc + hidb) * v, reduce over 4 lanes, atomicAdd
    float hcol[8], vcol[8];
    #pragma unroll
    for (int nn = 0; nn < 4; ++nn)
        #pragma unroll
        for (int bit = 0; bit < 2; ++bit) {
            int col = wn * 32 + nn * 8 + c * 2 + bit;
            hcol[nn * 2 + bit] = sh_hb[col];
            vcol[nn * 2 + bit] = sh_v[col];
        }

    #pragma unroll
    for (int mm = 0; mm < 4; ++mm) {
        float (*ac)[4] = (mm < 2) ? acc[mm] : acc2[mm - 2];
        float p0 = 0.0f, p1 = 0.0f;
        #pragma unroll
        for (int nn = 0; nn < 4; ++nn) {
            p0 += fast_tanh(ac[nn][0] + hcol[nn * 2 + 0]) * vcol[nn * 2 + 0];
            p0 += fast_tanh(ac[nn][1] + hcol[nn * 2 + 1]) * vcol[nn * 2 + 1];
            p1 += fast_tanh(ac[nn][2] + hcol[nn * 2 + 0]) * vcol[nn * 2 + 0];
            p1 += fast_tanh(ac[nn][3] + hcol[nn * 2 + 1]) * vcol[nn * 2 + 1];
        }
        p0 += __shfl_xor_sync(0xffffffffu, p0, 1);
        p0 += __shfl_xor_sync(0xffffffffu, p0, 2);
        p1 += __shfl_xor_sync(0xffffffffu, p1, 1);
        p1 += __shfl_xor_sync(0xffffffffu, p1, 2);
        if (c == 0) {
            int rbase = m0 + wm * 64 + mm * 16 + r;
            atomicAdd(&g_logits[rbase], p0);
            atomicAdd(&g_logits[rbase + 8], p1);
        }
    }
}

// ---------------------------------------------------------------------------
// Kernel 3: softmax over S per batch row
__global__ __launch_bounds__(256) void softmax_kernel(float* __restrict__ out) {
    __shared__ float red[256];
    int b = blockIdx.x;
    int t = threadIdx.x;
    const float* lg = g_logits + b * S_;

    float m = -1e30f;
    for (int i = t; i < S_; i += 256) m = fmaxf(m, lg[i]);
    red[t] = m;
    __syncthreads();
    for (int s = 128; s > 0; s >>= 1) {
        if (t < s) red[t] = fmaxf(red[t], red[t + s]);
        __syncthreads();
    }
    m = red[0];
    __syncthreads();

    float sum = 0.0f;
    for (int i = t; i < S_; i += 256) sum += expf(lg[i] - m);
    red[t] = sum;
    __syncthreads();
    for (int s = 128; s > 0; s >>= 1) {
        if (t < s) red[t] += red[t + s];
        __syncthreads();
    }
    float inv = 1.0f / red[0];

    for (int i = t; i < S_; i += 256) out[b * S_ + i] = expf(lg[i] - m) * inv;
}

// ---------------------------------------------------------------------------
extern "C" void kernel_launch(void* const* d_in, const int* in_sizes, int n_in,
                              void* d_out, int out_size) {
    const float* hidden  = (const float*)d_in[0];   // (16, 1024)
    const float* enc     = (const float*)d_in[1];   // (16, 2048, 1024)
    const float* W_attn  = (const float*)d_in[2];   // (2048, 1024)
    const float* b_attn  = (const float*)d_in[3];   // (1024,)
    const float* v       = (const float*)d_in[4];   // (1024,)
    float* out = (float*)d_out;                     // (16, 2048)

    cudaFuncSetAttribute(attn_gemm_kernel,
                         cudaFuncAttributeMaxDynamicSharedMemorySize, SMEM_TOTAL);

    conv_enc_kernel<<<(size_t)M_TOTAL * H_ / 8 / 256, 256>>>(enc);
    conv_w2t_kernel<<<dim3(32, 32), dim3(32, 8)>>>(W_attn);
    prep_kernel<<<dim3(4, 16), 256>>>(hidden, W_attn, b_attn);
    attn_gemm_kernel<<<dim3(H_ / BN, M_TOTAL / BM), 256, SMEM_TOTAL>>>(v);
    softmax_kernel<<<B_, 256>>>(out);
}

// round 7
// speedup vs baseline: 2.6518x; 1.0180x over previous
#include <cuda_runtime.h>
#include <cuda_fp16.h>
#include <stdint.h>

#define B_ 16
#define S_ 2048
#define H_ 1024
#define M_TOTAL (B_ * S_)   // 32768

#define BM 128
#define BN 128
#define BK 64
#define K_ITERS (H_ / BK)   // 16
#define NSTAGES 3

// Tile rows are 64 halves = 128B = 8 chunks of 16B, XOR-swizzled (c ^ (row&7))
#define A_BYTES (BM * 128)               // 16384
#define STAGE_BYTES (2 * A_BYTES)        // 32768
#define SMEM_TOTAL (NSTAGES * STAGE_BYTES + 1024)  // 99328

// Device scratch (static arrays only — no allocs allowed)
__device__ float g_hidb[B_ * H_];
__device__ float g_logits[M_TOTAL];
__device__ __align__(16) __half g_ench[(size_t)M_TOTAL * H_];  // enc fp16 (64MB)
__device__ __align__(16) __half g_w2th[(size_t)H_ * H_];       // W2^T fp16 [n][k]

// ---------------------------------------------------------------------------
#define CP_ASYNC16(dst, src) \
    asm volatile("cp.async.cg.shared.global [%0], [%1], 16;" :: "r"(dst), "l"(src))
#define CP_COMMIT() asm volatile("cp.async.commit_group;" ::: "memory")

__device__ __forceinline__ uint32_t smem_u32(const void* p) {
    uint32_t a;
    asm("{ .reg .u64 t; cvta.to.shared.u64 t, %1; cvt.u32.u64 %0, t; }" : "=r"(a) : "l"(p));
    return a;
}

// volatile: reads smem, must not be hoisted across barriers
__device__ __forceinline__ void ldmx4(uint32_t* r, uint32_t addr) {
    asm volatile("ldmatrix.sync.aligned.m8n8.x4.shared.b16 {%0,%1,%2,%3}, [%4];"
                 : "=r"(r[0]), "=r"(r[1]), "=r"(r[2]), "=r"(r[3]) : "r"(addr));
}

// NOT volatile: pure register op; dependencies tracked via constraints,
// lets the compiler interleave HMMA with subsequent LDSM.
__device__ __forceinline__ void mma_f16(float* d, const uint32_t* a, const uint32_t* b) {
    asm("mma.sync.aligned.m16n8k16.row.col.f32.f16.f16.f32 "
        "{%0,%1,%2,%3}, {%4,%5,%6,%7}, {%8,%9}, {%0,%1,%2,%3};\n"
        : "+f"(d[0]), "+f"(d[1]), "+f"(d[2]), "+f"(d[3])
        : "r"(a[0]), "r"(a[1]), "r"(a[2]), "r"(a[3]), "r"(b[0]), "r"(b[1]));
}

// Eigen/XLA rational tanh, FMA-pipe only. |err| ~ 1e-7 on [-8, 8].
__device__ __forceinline__ float fast_tanh(float x) {
    x = fminf(fmaxf(x, -7.99881172f), 7.99881172f);
    float x2 = x * x;
    float p = -2.76076847742355e-16f;
    p = fmaf(p, x2, 2.00018790482477e-13f);
    p = fmaf(p, x2, -8.60467152213735e-11f);
    p = fmaf(p, x2, 5.12229709037114e-08f);
    p = fmaf(p, x2, 1.48572235717979e-05f);
    p = fmaf(p, x2, 6.37261928875436e-04f);
    p = fmaf(p, x2, 4.89352455891786e-03f);
    p = p * x;
    float q = 1.19825839466702e-06f;
    q = fmaf(q, x2, 1.18534705686654e-04f);
    q = fmaf(q, x2, 2.26843463243900e-03f);
    q = fmaf(q, x2, 4.89352518554385e-03f);
    float r = __uint_as_float(0x7EF127EAu - __float_as_uint(q));
    r = r * (2.0f - q * r);
    r = r * (2.0f - q * r);
    r = r * (2.0f - q * r);
    return p * r;
}

// ---------------------------------------------------------------------------
// Kernel 0a: convert enc fp32 -> fp16 (8 elements per thread)
__global__ __launch_bounds__(256) void conv_enc_kernel(const float* __restrict__ enc) {
    size_t i = ((size_t)blockIdx.x * 256 + threadIdx.x) * 8;
    float4 v0 = *reinterpret_cast<const float4*>(enc + i);
    float4 v1 = *reinterpret_cast<const float4*>(enc + i + 4);
    __half2 h0 = __floats2half2_rn(v0.x, v0.y);
    __half2 h1 = __floats2half2_rn(v0.z, v0.w);
    __half2 h2 = __floats2half2_rn(v1.x, v1.y);
    __half2 h3 = __floats2half2_rn(v1.z, v1.w);
    uint4 u;
    u.x = *reinterpret_cast<uint32_t*>(&h0);
    u.y = *reinterpret_cast<uint32_t*>(&h1);
    u.z = *reinterpret_cast<uint32_t*>(&h2);
    u.w = *reinterpret_cast<uint32_t*>(&h3);
    *reinterpret_cast<uint4*>(&g_ench[i]) = u;
}

// ---------------------------------------------------------------------------
// Kernel 0b: transpose W2 -> g_w2th[n][k] fp16, + zero logits/hidb scratch
__global__ __launch_bounds__(256) void conv_w2t_kernel(const float* __restrict__ W_attn) {
    __shared__ float tile[32][33];
    int bx = blockIdx.x, by = blockIdx.y;
    int tx = threadIdx.x, ty = threadIdx.y;
    int n = bx * 32 + tx;
    #pragma unroll
    for (int j = 0; j < 32; j += 8)
        tile[ty + j][tx] = W_attn[(size_t)(H_ + by * 32 + ty + j) * H_ + n];
    __syncthreads();
    int k = by * 32 + tx;
    #pragma unroll
    for (int j = 0; j < 32; j += 8)
        g_w2th[(size_t)(bx * 32 + ty + j) * H_ + k] = __float2half_rn(tile[tx][ty + j]);

    int bid = by * 32 + bx;
    int t = ty * 32 + tx;
    if (bid < 64) {
        g_logits[bid * 512 + t] = 0.0f;
        g_logits[bid * 512 + t + 256] = 0.0f;
    } else if (bid < 128) {
        g_hidb[(bid - 64) * 256 + t] = 0.0f;
    }
}

// ---------------------------------------------------------------------------
// Kernel 1: g_hidb[b][n] += partial(hidden @ W1) + bias (k-split, W1 read once)
__global__ __launch_bounds__(256) void prep_kernel(
    const float* __restrict__ hidden,
    const float* __restrict__ W_attn,
    const float* __restrict__ b_attn)
{
    __shared__ float sh[16][64];
    int n = blockIdx.x * 256 + threadIdx.x;
    int k0 = blockIdx.y * 64;
    for (int i = threadIdx.x; i < 16 * 64; i += 256)
        sh[i >> 6][i & 63] = hidden[(i >> 6) * H_ + k0 + (i & 63)];
    __syncthreads();

    float acc[16];
    float bias = (blockIdx.y == 0) ? b_attn[n] : 0.0f;
    #pragma unroll
    for (int b = 0; b < 16; ++b) acc[b] = bias;

    #pragma unroll 8
    for (int k = 0; k < 64; ++k) {
        float w = W_attn[(size_t)(k0 + k) * H_ + n];
        #pragma unroll
        for (int b = 0; b < 16; ++b) acc[b] = fmaf(sh[b][k], w, acc[b]);
    }
    #pragma unroll
    for (int b = 0; b < 16; ++b) atomicAdd(&g_hidb[b * H_ + n], acc[b]);
}

// ---------------------------------------------------------------------------
// Kernel 2: fp16 mma GEMM, BK=64, 3-stage cp.async ring, 1 barrier/iter,
// refill deferred into the HMMA shadow, fragment loads interleaved with mma.
// grid (8 n-tiles, 256 m-tiles), 256 threads = 8 warps (2m x 4n), warp 64x32
__global__ __launch_bounds__(256, 2) void attn_gemm_kernel(
    const float* __restrict__ v)
{
    extern __shared__ char smem[];
    float* sh_hb = (float*)(smem + NSTAGES * STAGE_BYTES);
    float* sh_v  = sh_hb + BN;
    const uint32_t smem_base = smem_u32(smem);

    const int tid = threadIdx.x;
    const int lane = tid & 31;
    const int warp = tid >> 5;
    const int wm = warp >> 2;       // 0..1 (64-row slab)
    const int wn = warp & 3;        // 0..3 (32-col slab)
    const int r = lane >> 2;        // 0..7
    const int c = lane & 3;         // 0..3
    const int i8 = lane & 7;
    const int sub = lane >> 3;      // 0..3 (ldmatrix octet)

    const int m0 = blockIdx.y * BM;
    const int n0 = blockIdx.x * BN;
    const int batch = m0 >> 11;

    // --- cp.async addressing (fully strength-reduced) ---
    const int r0 = tid >> 3;
    const int cc = tid & 7;
    const uint32_t st_off = (uint32_t)r0 * 128u + (uint32_t)((cc ^ (r0 & 7)) << 4);
    const __half* a_g = &g_ench[(size_t)(m0 + r0) * H_ + cc * 8];
    const __half* b_g = &g_w2th[(size_t)(n0 + r0) * H_ + cc * 8];

    // --- ldmatrix addressing ---
    const uint32_t a_row  = (uint32_t)(wm * 64 + i8 + 8 * (sub & 1));
    const uint32_t a_csub = (uint32_t)(sub >> 1);
    const uint32_t a_x    = a_row & 7;
    const uint32_t a_base = a_row * 128u;
    const uint32_t b_row  = (uint32_t)(wn * 32 + i8 + 8 * (sub >> 1));
    const uint32_t b_csub = (uint32_t)(sub & 1);
    const uint32_t b_x    = b_row & 7;
    const uint32_t b_base = A_BYTES + b_row * 128u;

    if (tid < BN) {
        sh_hb[tid] = g_hidb[batch * H_ + n0 + tid];
        sh_v[tid]  = v[n0 + tid];
    }

    // prologue: stages 0,1
    #pragma unroll
    for (int s = 0; s < 2; ++s) {
        uint32_t sb = smem_base + s * STAGE_BYTES;
        #pragma unroll
        for (int p = 0; p < 4; ++p) {
            CP_ASYNC16(sb + st_off + p * 4096u, a_g + (size_t)p * 32 * H_);
            CP_ASYNC16(sb + A_BYTES + st_off + p * 4096u, b_g + (size_t)p * 32 * H_);
        }
        CP_COMMIT();
        a_g += BK; b_g += BK;
    }

    float acc[2][4][4];
    float acc2[2][4][4];
    #pragma unroll
    for (int mm = 0; mm < 2; ++mm)
        #pragma unroll
        for (int nn = 0; nn < 4; ++nn)
            #pragma unroll
            for (int i = 0; i < 4; ++i) { acc[mm][nn][i] = 0.0f; acc2[mm][nn][i] = 0.0f; }

    for (int i = 0; i < K_ITERS; ++i) {
        if (i == K_ITERS - 1) asm volatile("cp.async.wait_group 0;" ::: "memory");
        else                  asm volatile("cp.async.wait_group 1;" ::: "memory");
        __syncthreads();

        const uint32_t sa = smem_base + (i % NSTAGES) * STAGE_BYTES;
        const bool refill = (i + 2 < K_ITERS);
        const uint32_t sbb = smem_base + ((i + 2) % NSTAGES) * STAGE_BYTES;

        #pragma unroll
        for (int ks = 0; ks < 4; ++ks) {
            // B fragments first (needed by every mma of this ks)
            uint32_t bf[4][2];
            {
                uint32_t tmp[4];
                #pragma unroll
                for (int nnp = 0; nnp < 2; ++nnp) {
                    uint32_t addr = sa + b_base + nnp * (16u * 128u)
                                  + (((2 * ks + b_csub) ^ b_x) << 4);
                    ldmx4(tmp, addr);
                    bf[nnp * 2 + 0][0] = tmp[0];
                    bf[nnp * 2 + 0][1] = tmp[1];
                    bf[nnp * 2 + 1][0] = tmp[2];
                    bf[nnp * 2 + 1][1] = tmp[3];
                }
            }
            // Interleave A fragment loads with mma groups
            uint32_t af[4][4];
            {
                uint32_t addr0 = sa + a_base + (((2 * ks + a_csub) ^ a_x) << 4);
                ldmx4(af[0], addr0);
                #pragma unroll
                for (int mm = 0; mm < 4; ++mm) {
                    if (mm < 3)
                        ldmx4(af[mm + 1], addr0 + (uint32_t)(mm + 1) * (16u * 128u));
                    float (*ac)[4] = (mm < 2) ? acc[mm] : acc2[mm - 2];
                    #pragma unroll
                    for (int nn = 0; nn < 4; ++nn)
                        mma_f16(ac[nn], af[mm], bf[nn]);
                }
            }
            // Deferred refill: A-half after ks0, B-half after ks1 (HMMA shadow)
            if (ks == 0 && refill) {
                #pragma unroll
                for (int p = 0; p < 4; ++p)
                    CP_ASYNC16(sbb + st_off + p * 4096u, a_g + (size_t)p * 32 * H_);
            }
            if (ks == 1 && refill) {
                #pragma unroll
                for (int p = 0; p < 4; ++p)
                    CP_ASYNC16(sbb + A_BYTES + st_off + p * 4096u, b_g + (size_t)p * 32 * H_);
                CP_COMMIT();
                a_g += BK; b_g += BK;
            }
        }
    }

    // Epilogue: tanh(acc + hidb) * v, reduce over 4 lanes, atomicAdd
    float hcol[8], vcol[8];
    #pragma unroll
    for (int nn = 0; nn < 4; ++nn)
        #pragma unroll
        for (int bit = 0; bit < 2; ++bit) {
            int col = wn * 32 + nn * 8 + c * 2 + bit;
            hcol[nn * 2 + bit] = sh_hb[col];
            vcol[nn * 2 + bit] = sh_v[col];
        }

    #pragma unroll
    for (int mm = 0; mm < 4; ++mm) {
        float (*ac)[4] = (mm < 2) ? acc[mm] : acc2[mm - 2];
        float p0 = 0.0f, p1 = 0.0f;
        #pragma unroll
        for (int nn = 0; nn < 4; ++nn) {
            p0 += fast_tanh(ac[nn][0] + hcol[nn * 2 + 0]) * vcol[nn * 2 + 0];
            p0 += fast_tanh(ac[nn][1] + hcol[nn * 2 + 1]) * vcol[nn * 2 + 1];
            p1 += fast_tanh(ac[nn][2] + hcol[nn * 2 + 0]) * vcol[nn * 2 + 0];
            p1 += fast_tanh(ac[nn][3] + hcol[nn * 2 + 1]) * vcol[nn * 2 + 1];
        }
        p0 += __shfl_xor_sync(0xffffffffu, p0, 1);
        p0 += __shfl_xor_sync(0xffffffffu, p0, 2);
        p1 += __shfl_xor_sync(0xffffffffu, p1, 1);
        p1 += __shfl_xor_sync(0xffffffffu, p1, 2);
        if (c == 0) {
            int rbase = m0 + wm * 64 + mm * 16 + r;
            atomicAdd(&g_logits[rbase], p0);
            atomicAdd(&g_logits[rbase + 8], p1);
        }
    }
}

// ---------------------------------------------------------------------------
// Kernel 3: softmax over S per batch row
__global__ __launch_bounds__(256) void softmax_kernel(float* __restrict__ out) {
    __shared__ float red[256];
    int b = blockIdx.x;
    int t = threadIdx.x;
    const float* lg = g_logits + b * S_;

    float m = -1e30f;
    for (int i = t; i < S_; i += 256) m = fmaxf(m, lg[i]);
    red[t] = m;
    __syncthreads();
    for (int s = 128; s > 0; s >>= 1) {
        if (t < s) red[t] = fmaxf(red[t], red[t + s]);
        __syncthreads();
    }
    m = red[0];
    __syncthreads();

    float sum = 0.0f;
    for (int i = t; i < S_; i += 256) sum += expf(lg[i] - m);
    red[t] = sum;
    __syncthreads();
    for (int s = 128; s > 0; s >>= 1) {
        if (t < s) red[t] += red[t + s];
        __syncthreads();
    }
    float inv = 1.0f / red[0];

    for (int i = t; i < S_; i += 256) out[b * S_ + i] = expf(lg[i] - m) * inv;
}

// ---------------------------------------------------------------------------
extern "C" void kernel_launch(void* const* d_in, const int* in_sizes, int n_in,
                              void* d_out, int out_size) {
    const float* hidden  = (const float*)d_in[0];   // (16, 1024)
    const float* enc     = (const float*)d_in[1];   // (16, 2048, 1024)
    const float* W_attn  = (const float*)d_in[2];   // (2048, 1024)
    const float* b_attn  = (const float*)d_in[3];   // (1024,)
    const float* v       = (const float*)d_in[4];   // (1024,)
    float* out = (float*)d_out;                     // (16, 2048)

    cudaFuncSetAttribute(attn_gemm_kernel,
                         cudaFuncAttributeMaxDynamicSharedMemorySize, SMEM_TOTAL);

    conv_enc_kernel<<<(size_t)M_TOTAL * H_ / 8 / 256, 256>>>(enc);
    conv_w2t_kernel<<<dim3(32, 32), dim3(32, 8)>>>(W_attn);
    prep_kernel<<<dim3(4, 16), 256>>>(hidden, W_attn, b_attn);
    attn_gemm_kernel<<<dim3(H_ / BN, M_TOTAL / BM), 256, SMEM_TOTAL>>>(v);
    softmax_kernel<<<B_, 256>>>(out);
}